// round 1
// baseline (speedup 1.0000x reference)
#include <cuda_runtime.h>
#include <math.h>

#define BB 8
#define CIN 512
#define HH 64
#define WW 64
#define HWP 4096          // 64*64
#define NA 36864          // anchors per batch = 4096*9
#define NSORT 65536
#define NPRE 6000
#define NPOST 300

// output layout (floats)
#define OFF_CLS 0ull
#define OFF_LOC 589824ull
#define OFF_ROI 1769472ull
#define OFF_IDX 1779072ull

#define NEGINF (__int_as_float(0xff800000))

// ---------------- scratch (static device globals; no allocation) -------------
static __device__ float g_h[(size_t)BB * CIN * HWP];            // 64 MB conv output
static __device__ float g_wt[(size_t)CIN * 9 * CIN];            // transposed conv weights
static __device__ float g_roi[(size_t)BB * NA * 4];             // clipped boxes
static __device__ float g_score[(size_t)BB * NA];               // scores (-inf if invalid)
static __device__ unsigned long long g_keys[(size_t)BB * NSORT];// sort keys (padded)
static __device__ float g_nbox[(size_t)BB * NPRE * 4];          // gathered top-6000 boxes

// anchor base half-heights / half-widths (float32 of the np.float64 math)
__constant__ float c_h2[9] = {
    45.254833995939045f, 90.50966799187809f, 181.01933598375618f,
    64.0f, 128.0f, 256.0f,
    90.50966799187809f, 181.01933598375618f, 362.03867196751236f};
__constant__ float c_w2[9] = {
    90.50966799187809f, 181.01933598375618f, 362.03867196751236f,
    64.0f, 128.0f, 256.0f,
    45.254833995939045f, 90.50966799187809f, 181.01933598375618f};

// ---------------- 0: weight transpose  [oc][ic][3][3] -> [ic][k][oc] ---------
__global__ void wtrans_kernel(const float* __restrict__ w) {
    int idx = blockIdx.x * blockDim.x + threadIdx.x;
    if (idx >= CIN * CIN * 9) return;
    int kk = idx % 9;
    int ic = (idx / 9) % CIN;
    int oc = idx / (9 * CIN);
    g_wt[((size_t)ic * 9 + kk) * CIN + oc] = w[idx];
}

// ---------------- 1: 3x3 conv + bias + relu, fp32 ----------------------------
// block: 64 out-channels (blockIdx.x) x one row y (blockIdx.y) x batch (blockIdx.z)
// 256 threads = 16x16, each computes 4 oc x 4 x.
__global__ __launch_bounds__(256) void conv3x3_kernel(
    const float* __restrict__ x, const float* __restrict__ bias) {
    const int octile = blockIdx.x;   // 0..7
    const int y = blockIdx.y;        // 0..63
    const int b = blockIdx.z;        // 0..7
    const int tid = threadIdx.x;
    const int tx = tid & 15;
    const int ty = tid >> 4;

    __shared__ float s_in[8][3][66];
    __shared__ float s_w[8][9][64];

    float acc[4][4];
#pragma unroll
    for (int o = 0; o < 4; o++)
#pragma unroll
        for (int i = 0; i < 4; i++) acc[o][i] = 0.f;

    const float* xb = x + (size_t)b * CIN * HWP;

    for (int icg = 0; icg < CIN; icg += 8) {
        __syncthreads();
        // input rows y-1..y+1 with halo, 8 channels
        for (int t = tid; t < 8 * 3 * 66; t += 256) {
            int xx = t % 66;
            int r = (t / 66) % 3;
            int ic = t / 198;
            int gy = y + r - 1;
            int gx = xx - 1;
            float v = 0.f;
            if (gy >= 0 && gy < HH && gx >= 0 && gx < WW)
                v = xb[(size_t)(icg + ic) * HWP + gy * WW + gx];
            s_in[ic][r][xx] = v;
        }
        // weights [ic][k][oc]
        const float* wsrc = g_wt + (size_t)icg * 9 * CIN + octile * 64;
        for (int t = tid; t < 8 * 9 * 64; t += 256) {
            int oc = t & 63;
            int kk = (t >> 6) % 9;
            int ic = t / 576;
            s_w[ic][kk][oc] = wsrc[(size_t)(ic * 9 + kk) * CIN + oc];
        }
        __syncthreads();

#pragma unroll
        for (int ic = 0; ic < 8; ic++) {
#pragma unroll
            for (int ky = 0; ky < 3; ky++) {
                float xin[6];
#pragma unroll
                for (int i = 0; i < 6; i++) xin[i] = s_in[ic][ky][tx * 4 + i];
#pragma unroll
                for (int kx = 0; kx < 3; kx++) {
                    float4 w4 = *(const float4*)&s_w[ic][ky * 3 + kx][ty * 4];
#pragma unroll
                    for (int i = 0; i < 4; i++) {
                        acc[0][i] += w4.x * xin[i + kx];
                        acc[1][i] += w4.y * xin[i + kx];
                        acc[2][i] += w4.z * xin[i + kx];
                        acc[3][i] += w4.w * xin[i + kx];
                    }
                }
            }
        }
    }

    const int ocbase = octile * 64 + ty * 4;
#pragma unroll
    for (int o = 0; o < 4; o++) {
        float bv = bias[ocbase + o];
        float4 r;
        r.x = fmaxf(acc[o][0] + bv, 0.f);
        r.y = fmaxf(acc[o][1] + bv, 0.f);
        r.z = fmaxf(acc[o][2] + bv, 0.f);
        r.w = fmaxf(acc[o][3] + bv, 0.f);
        *(float4*)&g_h[((size_t)(b * CIN + ocbase + o)) * HWP + y * WW + tx * 4] = r;
    }
}

// ---------------- 2: heads (1x1 convs) + proposal prep -----------------------
// 256 blocks x 128 threads; each thread owns one pixel of one batch.
__global__ __launch_bounds__(128) void heads_kernel(
    const float* __restrict__ loc_w, const float* __restrict__ loc_b,
    const float* __restrict__ cls_w, const float* __restrict__ cls_b,
    const int* __restrict__ imh, const int* __restrict__ imw,
    float* __restrict__ out) {
    const int b = blockIdx.x >> 5;
    const int p = ((blockIdx.x & 31) << 7) + threadIdx.x;  // 0..4095

    __shared__ float s_w[64][54];

    float acc[54];
#pragma unroll
    for (int m = 0; m < 54; m++) acc[m] = 0.f;

    const float* hb = g_h + (size_t)b * CIN * HWP + p;

    for (int icg = 0; icg < CIN; icg += 64) {
        __syncthreads();
        for (int t = threadIdx.x; t < 64 * 54; t += 128) {
            int m = t % 54;
            int ic = t / 54;
            float wv = (m < 36) ? loc_w[m * CIN + icg + ic]
                                : cls_w[(m - 36) * CIN + icg + ic];
            s_w[ic][m] = wv;
        }
        __syncthreads();
        for (int ic = 0; ic < 64; ic++) {
            float hv = hb[(size_t)(icg + ic) * HWP];
#pragma unroll
            for (int m = 0; m < 54; m++) acc[m] += hv * s_w[ic][m];
        }
    }

    const float fh = (float)(*imh);
    const float fw = (float)(*imw);
    const int py = p >> 6, px = p & 63;
    const float sy = (float)py * 16.0f;
    const float sx = (float)px * 16.0f;

    const size_t cls_base = OFF_CLS + ((size_t)b * NA + (size_t)p * 9) * 2;
    const size_t loc_base = OFF_LOC + ((size_t)b * NA + (size_t)p * 9) * 4;

#pragma unroll
    for (int a = 0; a < 9; a++) {
        float dy = acc[4 * a + 0] + loc_b[4 * a + 0];
        float dx = acc[4 * a + 1] + loc_b[4 * a + 1];
        float dh = acc[4 * a + 2] + loc_b[4 * a + 2];
        float dw = acc[4 * a + 3] + loc_b[4 * a + 3];
        out[loc_base + a * 4 + 0] = dy;
        out[loc_base + a * 4 + 1] = dx;
        out[loc_base + a * 4 + 2] = dh;
        out[loc_base + a * 4 + 3] = dw;

        float v0 = acc[36 + 2 * a + 0] + cls_b[2 * a + 0];
        float v1 = acc[36 + 2 * a + 1] + cls_b[2 * a + 1];
        float c0 = 1.f / (1.f + expf(-v0));
        float c1 = 1.f / (1.f + expf(-v1));
        out[cls_base + a * 2 + 0] = c0;
        out[cls_base + a * 2 + 1] = c1;

        // anchor
        float a0 = -c_h2[a] + sy;
        float a1 = -c_w2[a] + sx;
        float a2 = c_h2[a] + sy;
        float a3 = c_w2[a] + sx;
        float hh = a2 - a0;
        float ww = a3 - a1;
        float cy = a0 + 0.5f * hh;
        float cx = a1 + 0.5f * ww;
        cy = cy + dy * hh;
        cx = cx + dx * ww;
        hh = hh * expf(dh);
        ww = ww * expf(dw);
        float r0 = cy - 0.5f * hh;
        float r1 = cx - 0.5f * ww;
        float r2 = cy + 0.5f * hh;
        float r3 = cx + 0.5f * ww;
        r0 = fminf(fmaxf(r0, 0.f), fh);
        r1 = fminf(fmaxf(r1, 0.f), fw);
        r2 = fminf(fmaxf(r2, 0.f), fh);
        r3 = fminf(fmaxf(r3, 0.f), fw);
        float hs = r2 - r0;
        float ws = r3 - r1;
        bool valid = (hs >= 16.0f) && (ws >= 16.0f);
        float sc = valid ? c1 : NEGINF;

        int i = p * 9 + a;
        float4 rb;
        rb.x = r0; rb.y = r1; rb.z = r2; rb.w = r3;
        *(float4*)&g_roi[((size_t)b * NA + i) * 4] = rb;
        g_score[(size_t)b * NA + i] = sc;
        unsigned uu = __float_as_uint(sc);
        uu = (uu & 0x80000000u) ? ~uu : (uu | 0x80000000u);
        g_keys[(size_t)b * NSORT + i] =
            ((unsigned long long)uu << 32) | (unsigned)(0xFFFFFFFFu - (unsigned)i);
    }
    // padding keys (7 per thread: 4096*7 = 28672 = 65536-36864)
#pragma unroll
    for (int k2 = 0; k2 < 7; k2++)
        g_keys[(size_t)b * NSORT + NA + p * 7 + k2] = 0ull;
}

// ---------------- 3: per-batch bitonic sort (ascending) ----------------------
__global__ __launch_bounds__(1024) void sort_kernel() {
    unsigned long long* d = g_keys + (size_t)blockIdx.x * NSORT;
    for (int k = 2; k <= NSORT; k <<= 1) {
        for (int j = k >> 1; j > 0; j >>= 1) {
            for (int t = threadIdx.x; t < NSORT; t += 1024) {
                int ixj = t ^ j;
                if (ixj > t) {
                    unsigned long long A = d[t];
                    unsigned long long Bv = d[ixj];
                    bool up = ((t & k) == 0);
                    bool sw = up ? (A > Bv) : (A < Bv);
                    if (sw) {
                        d[t] = Bv;
                        d[ixj] = A;
                    }
                }
            }
            __syncthreads();
        }
    }
}

// ---------------- 4: per-batch NMS -------------------------------------------
__global__ __launch_bounds__(256) void nms_kernel(float* __restrict__ out) {
    __shared__ float ss[NPRE];
    __shared__ unsigned char smask[NPRE];
    __shared__ int s_pick;

    const int b = blockIdx.x;
    const unsigned long long* kb = g_keys + (size_t)b * NSORT;
    float* nb = g_nbox + (size_t)b * NPRE * 4;

    // gather top-6000 (descending = from the top of ascending sort)
    for (int t = threadIdx.x; t < NPRE; t += blockDim.x) {
        unsigned long long key = kb[NSORT - 1 - t];
        unsigned ai = 0xFFFFFFFFu - (unsigned)(key & 0xFFFFFFFFull);
        *(float4*)&nb[(size_t)t * 4] =
            *(const float4*)&g_roi[((size_t)b * NA + ai) * 4];
        ss[t] = g_score[(size_t)b * NA + ai];
        smask[t] = 0;
    }
    // roi indices
    for (int t = threadIdx.x; t < NPOST; t += blockDim.x)
        out[OFF_IDX + (size_t)b * NPOST + t] = (float)b;
    __syncthreads();

    int ptr = 0;  // meaningful on thread 0 only
    for (int pick = 0; pick < NPOST; pick++) {
        if (threadIdx.x == 0) {
            while (ptr < NPRE && smask[ptr]) ptr++;
            if (ptr < NPRE && ss[ptr] != NEGINF) {
                s_pick = ptr;
                smask[ptr] = 1;
            } else {
                s_pick = -1;
            }
        }
        __syncthreads();
        int p = s_pick;
        if (p < 0) {
            int rem = (NPOST - pick) * 4;
            for (int t = threadIdx.x; t < rem; t += blockDim.x)
                out[OFF_ROI + ((size_t)b * NPOST + pick) * 4 + t] = 0.f;
            break;
        }
        float4 pb = *(const float4*)&nb[(size_t)p * 4];
        if (threadIdx.x == 0) {
            out[OFF_ROI + ((size_t)b * NPOST + pick) * 4 + 0] = pb.x;
            out[OFF_ROI + ((size_t)b * NPOST + pick) * 4 + 1] = pb.y;
            out[OFF_ROI + ((size_t)b * NPOST + pick) * 4 + 2] = pb.z;
            out[OFF_ROI + ((size_t)b * NPOST + pick) * 4 + 3] = pb.w;
        }
        float parea = (pb.z - pb.x) * (pb.w - pb.y);
        for (int j = p + 1 + threadIdx.x; j < NPRE; j += blockDim.x) {
            if (!smask[j]) {
                float4 q = *(const float4*)&nb[(size_t)j * 4];
                float yy1 = fmaxf(q.x, pb.x);
                float xx1 = fmaxf(q.y, pb.y);
                float yy2 = fminf(q.z, pb.z);
                float xx2 = fminf(q.w, pb.w);
                float inter = fmaxf(yy2 - yy1, 0.f) * fmaxf(xx2 - xx1, 0.f);
                float qarea = (q.z - q.x) * (q.w - q.y);
                float iou = inter / (qarea + parea - inter + 1e-9f);
                if (iou > 0.7f) smask[j] = 1;
            }
        }
        __syncthreads();
    }
}

// ---------------- launcher ---------------------------------------------------
extern "C" void kernel_launch(void* const* d_in, const int* in_sizes, int n_in,
                              void* d_out, int out_size) {
    const float* x = (const float*)d_in[0];
    const float* conv_w = (const float*)d_in[1];
    const float* conv_b = (const float*)d_in[2];
    const float* loc_w = (const float*)d_in[3];
    const float* loc_b = (const float*)d_in[4];
    const float* cls_w = (const float*)d_in[5];
    const float* cls_b = (const float*)d_in[6];
    const int* imh = (const int*)d_in[7];
    const int* imw = (const int*)d_in[8];
    float* out = (float*)d_out;

    wtrans_kernel<<<(CIN * CIN * 9 + 255) / 256, 256>>>(conv_w);
    conv3x3_kernel<<<dim3(8, 64, 8), 256>>>(x, conv_b);
    heads_kernel<<<256, 128>>>(loc_w, loc_b, cls_w, cls_b, imh, imw, out);
    sort_kernel<<<8, 1024>>>();
    nms_kernel<<<8, 256>>>(out);
}

// round 2
// speedup vs baseline: 1.3316x; 1.3316x over previous
#include <cuda_runtime.h>
#include <math.h>

#define BB 8
#define CIN 512
#define HH 64
#define WW 64
#define HWP 4096          // 64*64
#define NA 36864          // anchors per batch = 4096*9
#define NSORT 65536
#define NPRE 6000
#define NPOST 300

// output layout (floats)
#define OFF_CLS 0ull
#define OFF_LOC 589824ull
#define OFF_ROI 1769472ull
#define OFF_IDX 1779072ull

#define NEGINF (__int_as_float(0xff800000))

typedef unsigned long long ull;

// ---------------- packed f32x2 helpers (bitwise-identical IEEE fp32) ---------
__device__ __forceinline__ ull pack2(float x, float y) {
    ull r;
    asm("mov.b64 %0, {%1, %2};" : "=l"(r) : "f"(x), "f"(y));
    return r;
}
__device__ __forceinline__ float2 unpack2(ull v) {
    float2 r;
    asm("mov.b64 {%0, %1}, %2;" : "=f"(r.x), "=f"(r.y) : "l"(v));
    return r;
}
__device__ __forceinline__ void ffma2(ull& d, ull a, ull b) {
    asm("fma.rn.f32x2 %0, %1, %2, %0;" : "+l"(d) : "l"(a), "l"(b));
}

// ---------------- scratch (static device globals; no allocation) -------------
static __device__ float g_h[(size_t)BB * CIN * HWP];            // 64 MB conv output
static __device__ float g_wt[(size_t)CIN * 9 * CIN];            // transposed conv weights
static __device__ float g_roi[(size_t)BB * NA * 4];             // clipped boxes
static __device__ float g_score[(size_t)BB * NA];               // scores (-inf if invalid)
static __device__ ull g_keys[(size_t)BB * NSORT];               // sort keys (padded)
static __device__ float g_nbox[(size_t)BB * NPRE * 4];          // gathered top-6000 boxes

// anchor base half-heights / half-widths (float32 of the np.float64 math)
__constant__ float c_h2[9] = {
    45.254833995939045f, 90.50966799187809f, 181.01933598375618f,
    64.0f, 128.0f, 256.0f,
    90.50966799187809f, 181.01933598375618f, 362.03867196751236f};
__constant__ float c_w2[9] = {
    90.50966799187809f, 181.01933598375618f, 362.03867196751236f,
    64.0f, 128.0f, 256.0f,
    45.254833995939045f, 90.50966799187809f, 181.01933598375618f};

// ---------------- 0: weight transpose  [oc][ic][3][3] -> [ic][k][oc] ---------
__global__ void wtrans_kernel(const float* __restrict__ w) {
    int idx = blockIdx.x * blockDim.x + threadIdx.x;
    if (idx >= CIN * CIN * 9) return;
    int kk = idx % 9;
    int ic = (idx / 9) % CIN;
    int oc = idx / (9 * CIN);
    g_wt[((size_t)ic * 9 + kk) * CIN + oc] = w[idx];
}

// ---------------- 1: 3x3 conv + bias + relu, fp32 via FFMA2 ------------------
// block: 64 out-channels (blockIdx.x) x one row y (blockIdx.y) x batch (blockIdx.z)
// 256 threads = 16x16, each computes 4 oc x 4 x using packed f32x2 FMA
// (accumulators paired along oc; numerics bitwise identical to scalar fp32).
__global__ __launch_bounds__(256) void conv3x3_kernel(
    const float* __restrict__ x, const float* __restrict__ bias) {
    const int octile = blockIdx.x;   // 0..7
    const int y = blockIdx.y;        // 0..63
    const int b = blockIdx.z;        // 0..7
    const int tid = threadIdx.x;
    const int tx = tid & 15;
    const int ty = tid >> 4;

    __shared__ float s_in[8][3][66];
    __shared__ float s_w[8][9][64];

    // acc2[g][i] holds (acc[oc=2g][i], acc[oc=2g+1][i]) packed
    ull acc2[2][4];
#pragma unroll
    for (int g = 0; g < 2; g++)
#pragma unroll
        for (int i = 0; i < 4; i++) acc2[g][i] = pack2(0.f, 0.f);

    const float* xb = x + (size_t)b * CIN * HWP;

    for (int icg = 0; icg < CIN; icg += 8) {
        __syncthreads();
        // input rows y-1..y+1 with halo, 8 channels
        for (int t = tid; t < 8 * 3 * 66; t += 256) {
            int xx = t % 66;
            int r = (t / 66) % 3;
            int ic = t / 198;
            int gy = y + r - 1;
            int gx = xx - 1;
            float v = 0.f;
            if (gy >= 0 && gy < HH && gx >= 0 && gx < WW)
                v = xb[(size_t)(icg + ic) * HWP + gy * WW + gx];
            s_in[ic][r][xx] = v;
        }
        // weights [ic][k][oc]
        const float* wsrc = g_wt + (size_t)icg * 9 * CIN + octile * 64;
        for (int t = tid; t < 8 * 9 * 64; t += 256) {
            int oc = t & 63;
            int kk = (t >> 6) % 9;
            int ic = t / 576;
            s_w[ic][kk][oc] = wsrc[(size_t)(ic * 9 + kk) * CIN + oc];
        }
        __syncthreads();

#pragma unroll
        for (int ic = 0; ic < 8; ic++) {
#pragma unroll
            for (int ky = 0; ky < 3; ky++) {
                ull xp[6];
#pragma unroll
                for (int i = 0; i < 6; i++) {
                    float v = s_in[ic][ky][tx * 4 + i];
                    xp[i] = pack2(v, v);
                }
#pragma unroll
                for (int kx = 0; kx < 3; kx++) {
                    // weight pairs: (w[oc0],w[oc1]) and (w[oc2],w[oc3]) as 64b words
                    const ull* wp = (const ull*)&s_w[ic][ky * 3 + kx][ty * 4];
                    ull w01 = wp[0];
                    ull w23 = wp[1];
#pragma unroll
                    for (int i = 0; i < 4; i++) {
                        ffma2(acc2[0][i], xp[i + kx], w01);
                        ffma2(acc2[1][i], xp[i + kx], w23);
                    }
                }
            }
        }
    }

    float acc[4][4];
#pragma unroll
    for (int i = 0; i < 4; i++) {
        float2 u0 = unpack2(acc2[0][i]);
        float2 u1 = unpack2(acc2[1][i]);
        acc[0][i] = u0.x;
        acc[1][i] = u0.y;
        acc[2][i] = u1.x;
        acc[3][i] = u1.y;
    }

    const int ocbase = octile * 64 + ty * 4;
#pragma unroll
    for (int o = 0; o < 4; o++) {
        float bv = bias[ocbase + o];
        float4 r;
        r.x = fmaxf(acc[o][0] + bv, 0.f);
        r.y = fmaxf(acc[o][1] + bv, 0.f);
        r.z = fmaxf(acc[o][2] + bv, 0.f);
        r.w = fmaxf(acc[o][3] + bv, 0.f);
        *(float4*)&g_h[((size_t)(b * CIN + ocbase + o)) * HWP + y * WW + tx * 4] = r;
    }
}

// ---------------- 2: heads (1x1 convs) + proposal prep -----------------------
// 256 blocks x 128 threads; each thread owns one pixel of one batch.
__global__ __launch_bounds__(128) void heads_kernel(
    const float* __restrict__ loc_w, const float* __restrict__ loc_b,
    const float* __restrict__ cls_w, const float* __restrict__ cls_b,
    const int* __restrict__ imh, const int* __restrict__ imw,
    float* __restrict__ out) {
    const int b = blockIdx.x >> 5;
    const int p = ((blockIdx.x & 31) << 7) + threadIdx.x;  // 0..4095

    __shared__ float s_w[64][56];  // padded to 56 for 8B alignment of pairs

    ull acc2[27];
#pragma unroll
    for (int m = 0; m < 27; m++) acc2[m] = pack2(0.f, 0.f);

    const float* hb = g_h + (size_t)b * CIN * HWP + p;

    for (int icg = 0; icg < CIN; icg += 64) {
        __syncthreads();
        for (int t = threadIdx.x; t < 64 * 54; t += 128) {
            int m = t % 54;
            int ic = t / 54;
            float wv = (m < 36) ? loc_w[m * CIN + icg + ic]
                                : cls_w[(m - 36) * CIN + icg + ic];
            s_w[ic][m] = wv;
        }
        __syncthreads();
        for (int ic = 0; ic < 64; ic++) {
            float hv = hb[(size_t)(icg + ic) * HWP];
            ull hp = pack2(hv, hv);
            const ull* wrow = (const ull*)&s_w[ic][0];
#pragma unroll
            for (int m = 0; m < 27; m++) ffma2(acc2[m], hp, wrow[m]);
        }
    }

    float acc[54];
#pragma unroll
    for (int m = 0; m < 27; m++) {
        float2 u = unpack2(acc2[m]);
        acc[2 * m] = u.x;
        acc[2 * m + 1] = u.y;
    }

    const float fh = (float)(*imh);
    const float fw = (float)(*imw);
    const int py = p >> 6, px = p & 63;
    const float sy = (float)py * 16.0f;
    const float sx = (float)px * 16.0f;

    const size_t cls_base = OFF_CLS + ((size_t)b * NA + (size_t)p * 9) * 2;
    const size_t loc_base = OFF_LOC + ((size_t)b * NA + (size_t)p * 9) * 4;

#pragma unroll
    for (int a = 0; a < 9; a++) {
        float dy = acc[4 * a + 0] + loc_b[4 * a + 0];
        float dx = acc[4 * a + 1] + loc_b[4 * a + 1];
        float dh = acc[4 * a + 2] + loc_b[4 * a + 2];
        float dw = acc[4 * a + 3] + loc_b[4 * a + 3];
        out[loc_base + a * 4 + 0] = dy;
        out[loc_base + a * 4 + 1] = dx;
        out[loc_base + a * 4 + 2] = dh;
        out[loc_base + a * 4 + 3] = dw;

        float v0 = acc[36 + 2 * a + 0] + cls_b[2 * a + 0];
        float v1 = acc[36 + 2 * a + 1] + cls_b[2 * a + 1];
        float c0 = 1.f / (1.f + expf(-v0));
        float c1 = 1.f / (1.f + expf(-v1));
        out[cls_base + a * 2 + 0] = c0;
        out[cls_base + a * 2 + 1] = c1;

        // anchor decode + clip + min-size filter
        float a0 = -c_h2[a] + sy;
        float a1 = -c_w2[a] + sx;
        float a2 = c_h2[a] + sy;
        float a3 = c_w2[a] + sx;
        float hh = a2 - a0;
        float ww = a3 - a1;
        float cy = a0 + 0.5f * hh;
        float cx = a1 + 0.5f * ww;
        cy = cy + dy * hh;
        cx = cx + dx * ww;
        hh = hh * expf(dh);
        ww = ww * expf(dw);
        float r0 = cy - 0.5f * hh;
        float r1 = cx - 0.5f * ww;
        float r2 = cy + 0.5f * hh;
        float r3 = cx + 0.5f * ww;
        r0 = fminf(fmaxf(r0, 0.f), fh);
        r1 = fminf(fmaxf(r1, 0.f), fw);
        r2 = fminf(fmaxf(r2, 0.f), fh);
        r3 = fminf(fmaxf(r3, 0.f), fw);
        float hs = r2 - r0;
        float ws = r3 - r1;
        bool valid = (hs >= 16.0f) && (ws >= 16.0f);
        float sc = valid ? c1 : NEGINF;

        int i = p * 9 + a;
        float4 rb;
        rb.x = r0; rb.y = r1; rb.z = r2; rb.w = r3;
        *(float4*)&g_roi[((size_t)b * NA + i) * 4] = rb;
        g_score[(size_t)b * NA + i] = sc;
        unsigned uu = __float_as_uint(sc);
        uu = (uu & 0x80000000u) ? ~uu : (uu | 0x80000000u);
        g_keys[(size_t)b * NSORT + i] =
            ((ull)uu << 32) | (unsigned)(0xFFFFFFFFu - (unsigned)i);
    }
    // padding keys (7 per thread: 4096*7 = 28672 = 65536-36864)
#pragma unroll
    for (int k2 = 0; k2 < 7; k2++)
        g_keys[(size_t)b * NSORT + NA + p * 7 + k2] = 0ull;
}

// ---------------- 3: bitonic sort, smem-tiled --------------------------------
#define TILE 4096

// phase 1: sort each 4096-tile in shared memory (k = 2..4096)
__global__ __launch_bounds__(1024) void sort_phase1_kernel() {
    __shared__ ull s[TILE];
    const int batch = blockIdx.x >> 4;
    const int tile = blockIdx.x & 15;
    ull* d = g_keys + (size_t)batch * NSORT + (size_t)tile * TILE;
    const int gbase = tile * TILE;

    for (int t = threadIdx.x; t < TILE; t += 1024) s[t] = d[t];
    __syncthreads();

    for (int k = 2; k <= TILE; k <<= 1) {
        for (int j = k >> 1; j > 0; j >>= 1) {
            for (int t = threadIdx.x; t < TILE; t += 1024) {
                int ixj = t ^ j;
                if (ixj > t) {
                    ull A = s[t];
                    ull Bv = s[ixj];
                    bool up = (((gbase + t) & k) == 0);
                    if (up ? (A > Bv) : (A < Bv)) {
                        s[t] = Bv;
                        s[ixj] = A;
                    }
                }
            }
            __syncthreads();
        }
    }
    for (int t = threadIdx.x; t < TILE; t += 1024) d[t] = s[t];
}

// global step for j >= 4096 (crosses tiles)
__global__ __launch_bounds__(256) void sort_gstep_kernel(int k, int j) {
    int idx = blockIdx.x * blockDim.x + threadIdx.x;  // 0..BB*NSORT-1
    int b = idx >> 16;
    int t = idx & (NSORT - 1);
    ull* d = g_keys + (size_t)b * NSORT;
    int ixj = t ^ j;
    if (ixj > t) {
        ull A = d[t];
        ull Bv = d[ixj];
        bool up = ((t & k) == 0);
        if (up ? (A > Bv) : (A < Bv)) {
            d[t] = Bv;
            d[ixj] = A;
        }
    }
}

// smem tail of a merge phase: j = 2048..1 within tiles, for given k
__global__ __launch_bounds__(1024) void sort_sphase_kernel(int k) {
    __shared__ ull s[TILE];
    const int batch = blockIdx.x >> 4;
    const int tile = blockIdx.x & 15;
    ull* d = g_keys + (size_t)batch * NSORT + (size_t)tile * TILE;
    const int gbase = tile * TILE;

    for (int t = threadIdx.x; t < TILE; t += 1024) s[t] = d[t];
    __syncthreads();

    for (int j = TILE / 2; j > 0; j >>= 1) {
        for (int t = threadIdx.x; t < TILE; t += 1024) {
            int ixj = t ^ j;
            if (ixj > t) {
                ull A = s[t];
                ull Bv = s[ixj];
                bool up = (((gbase + t) & k) == 0);
                if (up ? (A > Bv) : (A < Bv)) {
                    s[t] = Bv;
                    s[ixj] = A;
                }
            }
        }
        __syncthreads();
    }
    for (int t = threadIdx.x; t < TILE; t += 1024) d[t] = s[t];
}

// ---------------- 4: per-batch NMS -------------------------------------------
__global__ __launch_bounds__(256) void nms_kernel(float* __restrict__ out) {
    __shared__ float ss[NPRE];
    __shared__ unsigned char smask[NPRE];
    __shared__ int s_pick;

    const int b = blockIdx.x;
    const ull* kb = g_keys + (size_t)b * NSORT;
    float* nb = g_nbox + (size_t)b * NPRE * 4;

    // gather top-6000 (descending = from the top of ascending sort)
    for (int t = threadIdx.x; t < NPRE; t += blockDim.x) {
        ull key = kb[NSORT - 1 - t];
        unsigned ai = 0xFFFFFFFFu - (unsigned)(key & 0xFFFFFFFFull);
        *(float4*)&nb[(size_t)t * 4] =
            *(const float4*)&g_roi[((size_t)b * NA + ai) * 4];
        ss[t] = g_score[(size_t)b * NA + ai];
        smask[t] = 0;
    }
    // roi indices
    for (int t = threadIdx.x; t < NPOST; t += blockDim.x)
        out[OFF_IDX + (size_t)b * NPOST + t] = (float)b;
    __syncthreads();

    int ptr = 0;  // meaningful on thread 0 only
    for (int pick = 0; pick < NPOST; pick++) {
        if (threadIdx.x == 0) {
            while (ptr < NPRE && smask[ptr]) ptr++;
            if (ptr < NPRE && ss[ptr] != NEGINF) {
                s_pick = ptr;
                smask[ptr] = 1;
            } else {
                s_pick = -1;
            }
        }
        __syncthreads();
        int p = s_pick;
        if (p < 0) {
            int rem = (NPOST - pick) * 4;
            for (int t = threadIdx.x; t < rem; t += blockDim.x)
                out[OFF_ROI + ((size_t)b * NPOST + pick) * 4 + t] = 0.f;
            break;
        }
        float4 pb = *(const float4*)&nb[(size_t)p * 4];
        if (threadIdx.x == 0) {
            out[OFF_ROI + ((size_t)b * NPOST + pick) * 4 + 0] = pb.x;
            out[OFF_ROI + ((size_t)b * NPOST + pick) * 4 + 1] = pb.y;
            out[OFF_ROI + ((size_t)b * NPOST + pick) * 4 + 2] = pb.z;
            out[OFF_ROI + ((size_t)b * NPOST + pick) * 4 + 3] = pb.w;
        }
        float parea = (pb.z - pb.x) * (pb.w - pb.y);
        for (int j = p + 1 + threadIdx.x; j < NPRE; j += blockDim.x) {
            if (!smask[j]) {
                float4 q = *(const float4*)&nb[(size_t)j * 4];
                float yy1 = fmaxf(q.x, pb.x);
                float xx1 = fmaxf(q.y, pb.y);
                float yy2 = fminf(q.z, pb.z);
                float xx2 = fminf(q.w, pb.w);
                float inter = fmaxf(yy2 - yy1, 0.f) * fmaxf(xx2 - xx1, 0.f);
                float qarea = (q.z - q.x) * (q.w - q.y);
                float iou = inter / (qarea + parea - inter + 1e-9f);
                if (iou > 0.7f) smask[j] = 1;
            }
        }
        __syncthreads();
    }
}

// ---------------- launcher ---------------------------------------------------
extern "C" void kernel_launch(void* const* d_in, const int* in_sizes, int n_in,
                              void* d_out, int out_size) {
    const float* x = (const float*)d_in[0];
    const float* conv_w = (const float*)d_in[1];
    const float* conv_b = (const float*)d_in[2];
    const float* loc_w = (const float*)d_in[3];
    const float* loc_b = (const float*)d_in[4];
    const float* cls_w = (const float*)d_in[5];
    const float* cls_b = (const float*)d_in[6];
    const int* imh = (const int*)d_in[7];
    const int* imw = (const int*)d_in[8];
    float* out = (float*)d_out;

    wtrans_kernel<<<(CIN * CIN * 9 + 255) / 256, 256>>>(conv_w);
    conv3x3_kernel<<<dim3(8, 64, 8), 256>>>(x, conv_b);
    heads_kernel<<<256, 128>>>(loc_w, loc_b, cls_w, cls_b, imh, imw, out);

    sort_phase1_kernel<<<128, 1024>>>();
    for (int k = 8192; k <= NSORT; k <<= 1) {
        for (int j = k >> 1; j >= TILE; j >>= 1)
            sort_gstep_kernel<<<(BB * NSORT) / 256, 256>>>(k, j);
        sort_sphase_kernel<<<128, 1024>>>(k);
    }

    nms_kernel<<<8, 256>>>(out);
}

// round 3
// speedup vs baseline: 1.5842x; 1.1897x over previous
#include <cuda_runtime.h>
#include <math.h>

#define BB 8
#define CIN 512
#define HH 64
#define WW 64
#define HWP 4096          // 64*64
#define NA 36864          // anchors per batch = 4096*9
#define NSORT 65536
#define NPRE 6000
#define NPOST 300

// output layout (floats)
#define OFF_CLS 0ull
#define OFF_LOC 589824ull
#define OFF_ROI 1769472ull
#define OFF_IDX 1779072ull

#define NEGINF (__int_as_float(0xff800000))

typedef unsigned long long ull;

// ---------------- packed f32x2 helpers (bitwise-identical IEEE fp32) ---------
__device__ __forceinline__ ull pack2(float x, float y) {
    ull r;
    asm("mov.b64 %0, {%1, %2};" : "=l"(r) : "f"(x), "f"(y));
    return r;
}
__device__ __forceinline__ float2 unpack2(ull v) {
    float2 r;
    asm("mov.b64 {%0, %1}, %2;" : "=f"(r.x), "=f"(r.y) : "l"(v));
    return r;
}
__device__ __forceinline__ void ffma2(ull& d, ull a, ull b) {
    asm("fma.rn.f32x2 %0, %1, %2, %0;" : "+l"(d) : "l"(a), "l"(b));
}

// ---------------- scratch (static device globals; no allocation) -------------
static __device__ float g_h[(size_t)BB * CIN * HWP];            // 64 MB conv output
static __device__ float g_wt[(size_t)CIN * 9 * CIN];            // transposed conv weights
static __device__ float g_roi[(size_t)BB * NA * 4];             // clipped boxes
static __device__ float g_score[(size_t)BB * NA];               // scores (-inf if invalid)
static __device__ ull g_keys[(size_t)BB * NSORT];               // sort keys (padded)
static __device__ float g_nbox[(size_t)BB * NPRE * 4];          // gathered top-6000 boxes

// anchor base half-heights / half-widths (float32 of the np.float64 math)
__constant__ float c_h2[9] = {
    45.254833995939045f, 90.50966799187809f, 181.01933598375618f,
    64.0f, 128.0f, 256.0f,
    90.50966799187809f, 181.01933598375618f, 362.03867196751236f};
__constant__ float c_w2[9] = {
    90.50966799187809f, 181.01933598375618f, 362.03867196751236f,
    64.0f, 128.0f, 256.0f,
    45.254833995939045f, 90.50966799187809f, 181.01933598375618f};

// ---------------- 0: weight transpose  [oc][ic][3][3] -> [ic][k][oc] ---------
__global__ void wtrans_kernel(const float* __restrict__ w) {
    int idx = blockIdx.x * blockDim.x + threadIdx.x;
    if (idx >= CIN * CIN * 9) return;
    int kk = idx % 9;
    int ic = (idx / 9) % CIN;
    int oc = idx / (9 * CIN);
    g_wt[((size_t)ic * 9 + kk) * CIN + oc] = w[idx];
}

// ---------------- 1: 3x3 conv + bias + relu, fp32 via FFMA2 ------------------
// Block: 64 oc (blockIdx.x) x 4 rows (blockIdx.y) x batch (blockIdx.z), 256 thr.
// Thread tile: 8 oc x 8 px.  tx = tid&31 -> (row = tx>>3, X0 = (tx&7)*8),
// ty = tid>>5 (warp id) -> oc group; ALL weight LDS are warp-uniform broadcast.
// Accumulation order over (ic, ky, kx) identical to prior rounds -> bitwise
// identical outputs.
__global__ __launch_bounds__(256) void conv3x3_kernel(
    const float* __restrict__ x, const float* __restrict__ bias) {
    const int octile = blockIdx.x;   // 0..7   (oc base = octile*64)
    const int y0 = blockIdx.y * 4;   // rows y0..y0+3
    const int b = blockIdx.z;        // 0..7
    const int tid = threadIdx.x;
    const int tx = tid & 31;
    const int ty = tid >> 5;         // warp id = oc subgroup 0..7
    const int r_out = tx >> 3;       // 0..3 row within block
    const int X0 = (tx & 7) * 8;     // x base, 8 px per thread

    __shared__ float s_in[8][6][68];   // rows y0-1 .. y0+4, col c <-> x = c-1
    __shared__ float s_w[8][9][64];

    // acc2[g][i]: packed (acc[oc=2g], acc[oc=2g+1]) for px i
    ull acc2[4][8];
#pragma unroll
    for (int g = 0; g < 4; g++)
#pragma unroll
        for (int i = 0; i < 8; i++) acc2[g][i] = pack2(0.f, 0.f);

    const float* xb = x + (size_t)b * CIN * HWP;

    for (int icg = 0; icg < CIN; icg += 8) {
        __syncthreads();
        // input rows y0-1..y0+4 with x halo, 8 channels (8*6*66 used cols)
        for (int t = tid; t < 8 * 6 * 66; t += 256) {
            int xx = t % 66;
            int r = (t / 66) % 6;
            int ic = t / 396;
            int gy = y0 + r - 1;
            int gx = xx - 1;
            float v = 0.f;
            if (gy >= 0 && gy < HH && gx >= 0 && gx < WW)
                v = xb[(size_t)(icg + ic) * HWP + gy * WW + gx];
            s_in[ic][r][xx] = v;
        }
        // weights [ic][k][oc]
        const float* wsrc = g_wt + (size_t)icg * 9 * CIN + octile * 64;
        for (int t = tid; t < 8 * 9 * 64; t += 256) {
            int oc = t & 63;
            int kk = (t >> 6) % 9;
            int ic = t / 576;
            s_w[ic][kk][oc] = wsrc[(size_t)(ic * 9 + kk) * CIN + oc];
        }
        __syncthreads();

#pragma unroll
        for (int ic = 0; ic < 8; ic++) {
#pragma unroll
            for (int ky = 0; ky < 3; ky++) {
                // 10 input cols X0..X0+9 (16B-aligned: row stride 68 words)
                const float* irow = &s_in[ic][r_out + ky][X0];
                float4 f0 = *(const float4*)(irow);
                float4 f1 = *(const float4*)(irow + 4);
                float2 f2 = *(const float2*)(irow + 8);
                ull xp[10];
                xp[0] = pack2(f0.x, f0.x); xp[1] = pack2(f0.y, f0.y);
                xp[2] = pack2(f0.z, f0.z); xp[3] = pack2(f0.w, f0.w);
                xp[4] = pack2(f1.x, f1.x); xp[5] = pack2(f1.y, f1.y);
                xp[6] = pack2(f1.z, f1.z); xp[7] = pack2(f1.w, f1.w);
                xp[8] = pack2(f2.x, f2.x); xp[9] = pack2(f2.y, f2.y);
#pragma unroll
                for (int kx = 0; kx < 3; kx++) {
                    // 8 oc weights, warp-uniform address (ty const per warp)
                    const ull* wp = (const ull*)&s_w[ic][ky * 3 + kx][ty * 8];
                    ull w01 = wp[0];
                    ull w23 = wp[1];
                    ull w45 = wp[2];
                    ull w67 = wp[3];
#pragma unroll
                    for (int i = 0; i < 8; i++) {
                        ffma2(acc2[0][i], xp[i + kx], w01);
                        ffma2(acc2[1][i], xp[i + kx], w23);
                        ffma2(acc2[2][i], xp[i + kx], w45);
                        ffma2(acc2[3][i], xp[i + kx], w67);
                    }
                }
            }
        }
    }

    const int ocbase = octile * 64 + ty * 8;
    const int yrow = y0 + r_out;
#pragma unroll
    for (int g = 0; g < 4; g++) {
        float bv0 = bias[ocbase + 2 * g];
        float bv1 = bias[ocbase + 2 * g + 1];
        float r0[8], r1[8];
#pragma unroll
        for (int i = 0; i < 8; i++) {
            float2 u = unpack2(acc2[g][i]);
            r0[i] = fmaxf(u.x + bv0, 0.f);
            r1[i] = fmaxf(u.y + bv1, 0.f);
        }
        float* d0 = &g_h[((size_t)(b * CIN + ocbase + 2 * g)) * HWP + yrow * WW + X0];
        float* d1 = &g_h[((size_t)(b * CIN + ocbase + 2 * g + 1)) * HWP + yrow * WW + X0];
        *(float4*)(d0)     = make_float4(r0[0], r0[1], r0[2], r0[3]);
        *(float4*)(d0 + 4) = make_float4(r0[4], r0[5], r0[6], r0[7]);
        *(float4*)(d1)     = make_float4(r1[0], r1[1], r1[2], r1[3]);
        *(float4*)(d1 + 4) = make_float4(r1[4], r1[5], r1[6], r1[7]);
    }
}

// ---------------- 2: heads (1x1 convs) + proposal prep -----------------------
// 256 blocks x 128 threads; each thread owns one pixel of one batch.
__global__ __launch_bounds__(128) void heads_kernel(
    const float* __restrict__ loc_w, const float* __restrict__ loc_b,
    const float* __restrict__ cls_w, const float* __restrict__ cls_b,
    const int* __restrict__ imh, const int* __restrict__ imw,
    float* __restrict__ out) {
    const int b = blockIdx.x >> 5;
    const int p = ((blockIdx.x & 31) << 7) + threadIdx.x;  // 0..4095

    __shared__ float s_w[64][56];  // padded to 56 for 8B alignment of pairs

    ull acc2[27];
#pragma unroll
    for (int m = 0; m < 27; m++) acc2[m] = pack2(0.f, 0.f);

    const float* hb = g_h + (size_t)b * CIN * HWP + p;

    for (int icg = 0; icg < CIN; icg += 64) {
        __syncthreads();
        for (int t = threadIdx.x; t < 64 * 54; t += 128) {
            int m = t % 54;
            int ic = t / 54;
            float wv = (m < 36) ? loc_w[m * CIN + icg + ic]
                                : cls_w[(m - 36) * CIN + icg + ic];
            s_w[ic][m] = wv;
        }
        __syncthreads();
        for (int ic = 0; ic < 64; ic++) {
            float hv = hb[(size_t)(icg + ic) * HWP];
            ull hp = pack2(hv, hv);
            const ull* wrow = (const ull*)&s_w[ic][0];
#pragma unroll
            for (int m = 0; m < 27; m++) ffma2(acc2[m], hp, wrow[m]);
        }
    }

    float acc[54];
#pragma unroll
    for (int m = 0; m < 27; m++) {
        float2 u = unpack2(acc2[m]);
        acc[2 * m] = u.x;
        acc[2 * m + 1] = u.y;
    }

    const float fh = (float)(*imh);
    const float fw = (float)(*imw);
    const int py = p >> 6, px = p & 63;
    const float sy = (float)py * 16.0f;
    const float sx = (float)px * 16.0f;

    const size_t cls_base = OFF_CLS + ((size_t)b * NA + (size_t)p * 9) * 2;
    const size_t loc_base = OFF_LOC + ((size_t)b * NA + (size_t)p * 9) * 4;

#pragma unroll
    for (int a = 0; a < 9; a++) {
        float dy = acc[4 * a + 0] + loc_b[4 * a + 0];
        float dx = acc[4 * a + 1] + loc_b[4 * a + 1];
        float dh = acc[4 * a + 2] + loc_b[4 * a + 2];
        float dw = acc[4 * a + 3] + loc_b[4 * a + 3];
        out[loc_base + a * 4 + 0] = dy;
        out[loc_base + a * 4 + 1] = dx;
        out[loc_base + a * 4 + 2] = dh;
        out[loc_base + a * 4 + 3] = dw;

        float v0 = acc[36 + 2 * a + 0] + cls_b[2 * a + 0];
        float v1 = acc[36 + 2 * a + 1] + cls_b[2 * a + 1];
        float c0 = 1.f / (1.f + expf(-v0));
        float c1 = 1.f / (1.f + expf(-v1));
        out[cls_base + a * 2 + 0] = c0;
        out[cls_base + a * 2 + 1] = c1;

        // anchor decode + clip + min-size filter
        float a0 = -c_h2[a] + sy;
        float a1 = -c_w2[a] + sx;
        float a2 = c_h2[a] + sy;
        float a3 = c_w2[a] + sx;
        float hh = a2 - a0;
        float ww = a3 - a1;
        float cy = a0 + 0.5f * hh;
        float cx = a1 + 0.5f * ww;
        cy = cy + dy * hh;
        cx = cx + dx * ww;
        hh = hh * expf(dh);
        ww = ww * expf(dw);
        float r0 = cy - 0.5f * hh;
        float r1 = cx - 0.5f * ww;
        float r2 = cy + 0.5f * hh;
        float r3 = cx + 0.5f * ww;
        r0 = fminf(fmaxf(r0, 0.f), fh);
        r1 = fminf(fmaxf(r1, 0.f), fw);
        r2 = fminf(fmaxf(r2, 0.f), fh);
        r3 = fminf(fmaxf(r3, 0.f), fw);
        float hs = r2 - r0;
        float ws = r3 - r1;
        bool valid = (hs >= 16.0f) && (ws >= 16.0f);
        float sc = valid ? c1 : NEGINF;

        int i = p * 9 + a;
        float4 rb;
        rb.x = r0; rb.y = r1; rb.z = r2; rb.w = r3;
        *(float4*)&g_roi[((size_t)b * NA + i) * 4] = rb;
        g_score[(size_t)b * NA + i] = sc;
        unsigned uu = __float_as_uint(sc);
        uu = (uu & 0x80000000u) ? ~uu : (uu | 0x80000000u);
        g_keys[(size_t)b * NSORT + i] =
            ((ull)uu << 32) | (unsigned)(0xFFFFFFFFu - (unsigned)i);
    }
    // padding keys (7 per thread: 4096*7 = 28672 = 65536-36864)
#pragma unroll
    for (int k2 = 0; k2 < 7; k2++)
        g_keys[(size_t)b * NSORT + NA + p * 7 + k2] = 0ull;
}

// ---------------- 3: bitonic sort, smem-tiled --------------------------------
#define TILE 4096

// phase 1: sort each 4096-tile in shared memory (k = 2..4096)
__global__ __launch_bounds__(1024) void sort_phase1_kernel() {
    __shared__ ull s[TILE];
    const int batch = blockIdx.x >> 4;
    const int tile = blockIdx.x & 15;
    ull* d = g_keys + (size_t)batch * NSORT + (size_t)tile * TILE;
    const int gbase = tile * TILE;

    for (int t = threadIdx.x; t < TILE; t += 1024) s[t] = d[t];
    __syncthreads();

    for (int k = 2; k <= TILE; k <<= 1) {
        for (int j = k >> 1; j > 0; j >>= 1) {
            for (int t = threadIdx.x; t < TILE; t += 1024) {
                int ixj = t ^ j;
                if (ixj > t) {
                    ull A = s[t];
                    ull Bv = s[ixj];
                    bool up = (((gbase + t) & k) == 0);
                    if (up ? (A > Bv) : (A < Bv)) {
                        s[t] = Bv;
                        s[ixj] = A;
                    }
                }
            }
            __syncthreads();
        }
    }
    for (int t = threadIdx.x; t < TILE; t += 1024) d[t] = s[t];
}

// global step for j >= 4096 (crosses tiles)
__global__ __launch_bounds__(256) void sort_gstep_kernel(int k, int j) {
    int idx = blockIdx.x * blockDim.x + threadIdx.x;  // 0..BB*NSORT-1
    int b = idx >> 16;
    int t = idx & (NSORT - 1);
    ull* d = g_keys + (size_t)b * NSORT;
    int ixj = t ^ j;
    if (ixj > t) {
        ull A = d[t];
        ull Bv = d[ixj];
        bool up = ((t & k) == 0);
        if (up ? (A > Bv) : (A < Bv)) {
            d[t] = Bv;
            d[ixj] = A;
        }
    }
}

// smem tail of a merge phase: j = 2048..1 within tiles, for given k
__global__ __launch_bounds__(1024) void sort_sphase_kernel(int k) {
    __shared__ ull s[TILE];
    const int batch = blockIdx.x >> 4;
    const int tile = blockIdx.x & 15;
    ull* d = g_keys + (size_t)batch * NSORT + (size_t)tile * TILE;
    const int gbase = tile * TILE;

    for (int t = threadIdx.x; t < TILE; t += 1024) s[t] = d[t];
    __syncthreads();

    for (int j = TILE / 2; j > 0; j >>= 1) {
        for (int t = threadIdx.x; t < TILE; t += 1024) {
            int ixj = t ^ j;
            if (ixj > t) {
                ull A = s[t];
                ull Bv = s[ixj];
                bool up = (((gbase + t) & k) == 0);
                if (up ? (A > Bv) : (A < Bv)) {
                    s[t] = Bv;
                    s[ixj] = A;
                }
            }
        }
        __syncthreads();
    }
    for (int t = threadIdx.x; t < TILE; t += 1024) d[t] = s[t];
}

// ---------------- 4: per-batch NMS -------------------------------------------
__global__ __launch_bounds__(256) void nms_kernel(float* __restrict__ out) {
    __shared__ float ss[NPRE];
    __shared__ unsigned char smask[NPRE];
    __shared__ int s_pick;

    const int b = blockIdx.x;
    const ull* kb = g_keys + (size_t)b * NSORT;
    float* nb = g_nbox + (size_t)b * NPRE * 4;

    // gather top-6000 (descending = from the top of ascending sort)
    for (int t = threadIdx.x; t < NPRE; t += blockDim.x) {
        ull key = kb[NSORT - 1 - t];
        unsigned ai = 0xFFFFFFFFu - (unsigned)(key & 0xFFFFFFFFull);
        *(float4*)&nb[(size_t)t * 4] =
            *(const float4*)&g_roi[((size_t)b * NA + ai) * 4];
        ss[t] = g_score[(size_t)b * NA + ai];
        smask[t] = 0;
    }
    // roi indices
    for (int t = threadIdx.x; t < NPOST; t += blockDim.x)
        out[OFF_IDX + (size_t)b * NPOST + t] = (float)b;
    __syncthreads();

    int ptr = 0;  // meaningful on thread 0 only
    for (int pick = 0; pick < NPOST; pick++) {
        if (threadIdx.x == 0) {
            while (ptr < NPRE && smask[ptr]) ptr++;
            if (ptr < NPRE && ss[ptr] != NEGINF) {
                s_pick = ptr;
                smask[ptr] = 1;
            } else {
                s_pick = -1;
            }
        }
        __syncthreads();
        int p = s_pick;
        if (p < 0) {
            int rem = (NPOST - pick) * 4;
            for (int t = threadIdx.x; t < rem; t += blockDim.x)
                out[OFF_ROI + ((size_t)b * NPOST + pick) * 4 + t] = 0.f;
            break;
        }
        float4 pb = *(const float4*)&nb[(size_t)p * 4];
        if (threadIdx.x == 0) {
            out[OFF_ROI + ((size_t)b * NPOST + pick) * 4 + 0] = pb.x;
            out[OFF_ROI + ((size_t)b * NPOST + pick) * 4 + 1] = pb.y;
            out[OFF_ROI + ((size_t)b * NPOST + pick) * 4 + 2] = pb.z;
            out[OFF_ROI + ((size_t)b * NPOST + pick) * 4 + 3] = pb.w;
        }
        float parea = (pb.z - pb.x) * (pb.w - pb.y);
        for (int j = p + 1 + threadIdx.x; j < NPRE; j += blockDim.x) {
            if (!smask[j]) {
                float4 q = *(const float4*)&nb[(size_t)j * 4];
                float yy1 = fmaxf(q.x, pb.x);
                float xx1 = fmaxf(q.y, pb.y);
                float yy2 = fminf(q.z, pb.z);
                float xx2 = fminf(q.w, pb.w);
                float inter = fmaxf(yy2 - yy1, 0.f) * fmaxf(xx2 - xx1, 0.f);
                float qarea = (q.z - q.x) * (q.w - q.y);
                float iou = inter / (qarea + parea - inter + 1e-9f);
                if (iou > 0.7f) smask[j] = 1;
            }
        }
        __syncthreads();
    }
}

// ---------------- launcher ---------------------------------------------------
extern "C" void kernel_launch(void* const* d_in, const int* in_sizes, int n_in,
                              void* d_out, int out_size) {
    const float* x = (const float*)d_in[0];
    const float* conv_w = (const float*)d_in[1];
    const float* conv_b = (const float*)d_in[2];
    const float* loc_w = (const float*)d_in[3];
    const float* loc_b = (const float*)d_in[4];
    const float* cls_w = (const float*)d_in[5];
    const float* cls_b = (const float*)d_in[6];
    const int* imh = (const int*)d_in[7];
    const int* imw = (const int*)d_in[8];
    float* out = (float*)d_out;

    wtrans_kernel<<<(CIN * CIN * 9 + 255) / 256, 256>>>(conv_w);
    conv3x3_kernel<<<dim3(8, 16, 8), 256>>>(x, conv_b);
    heads_kernel<<<256, 128>>>(loc_w, loc_b, cls_w, cls_b, imh, imw, out);

    sort_phase1_kernel<<<128, 1024>>>();
    for (int k = 8192; k <= NSORT; k <<= 1) {
        for (int j = k >> 1; j >= TILE; j >>= 1)
            sort_gstep_kernel<<<(BB * NSORT) / 256, 256>>>(k, j);
        sort_sphase_kernel<<<128, 1024>>>(k);
    }

    nms_kernel<<<8, 256>>>(out);
}

// round 7
// speedup vs baseline: 1.6507x; 1.0419x over previous
#include <cuda_runtime.h>
#include <math.h>
#include <cstdint>

#define BB 8
#define CIN 512
#define HH 64
#define WW 64
#define HWP 4096          // 64*64
#define NA 36864          // anchors per batch = 4096*9
#define NSORT 65536
#define NPRE 6000
#define NPOST 300

// output layout (floats)
#define OFF_CLS 0ull
#define OFF_LOC 589824ull
#define OFF_ROI 1769472ull
#define OFF_IDX 1779072ull

#define NEGINF (__int_as_float(0xff800000))

typedef unsigned long long ull;

// ---------------- packed f32x2 helpers (bitwise-identical IEEE fp32) ---------
__device__ __forceinline__ ull pack2(float x, float y) {
    ull r;
    asm("mov.b64 %0, {%1, %2};" : "=l"(r) : "f"(x), "f"(y));
    return r;
}
__device__ __forceinline__ float2 unpack2(ull v) {
    float2 r;
    asm("mov.b64 {%0, %1}, %2;" : "=f"(r.x), "=f"(r.y) : "l"(v));
    return r;
}
__device__ __forceinline__ void ffma2(ull& d, ull a, ull b) {
    asm("fma.rn.f32x2 %0, %1, %2, %0;" : "+l"(d) : "l"(a), "l"(b));
}

__device__ __forceinline__ uint32_t smem_u32(const void* p) {
    uint32_t a;
    asm("{ .reg .u64 t; cvta.to.shared.u64 t, %1; cvt.u32.u64 %0, t; }"
        : "=r"(a) : "l"(p));
    return a;
}
#define CP_COMMIT() asm volatile("cp.async.commit_group;" ::: "memory")
#define CP_WAIT1()  asm volatile("cp.async.wait_group 1;" ::: "memory")
#define CP_WAIT0()  asm volatile("cp.async.wait_group 0;" ::: "memory")

// ---------------- scratch (static device globals; no allocation) -------------
static __device__ float g_h[(size_t)BB * CIN * HWP];            // 64 MB conv output
static __device__ float g_wt[(size_t)CIN * 9 * CIN];            // transposed conv weights
static __device__ float g_roi[(size_t)BB * NA * 4];             // clipped boxes
static __device__ float g_score[(size_t)BB * NA];               // scores (-inf if invalid)
static __device__ ull g_keys[(size_t)BB * NSORT];               // sort keys (padded)
static __device__ float g_nbox[(size_t)BB * NPRE * 4];          // gathered top-6000 boxes

// anchor base half-heights / half-widths (float32 of the np.float64 math)
__constant__ float c_h2[9] = {
    45.254833995939045f, 90.50966799187809f, 181.01933598375618f,
    64.0f, 128.0f, 256.0f,
    90.50966799187809f, 181.01933598375618f, 362.03867196751236f};
__constant__ float c_w2[9] = {
    90.50966799187809f, 181.01933598375618f, 362.03867196751236f,
    64.0f, 128.0f, 256.0f,
    45.254833995939045f, 90.50966799187809f, 181.01933598375618f};

// ---------------- 0: weight transpose  [oc][ic][3][3] -> [ic][k][oc] ---------
__global__ void wtrans_kernel(const float* __restrict__ w) {
    int idx = blockIdx.x * blockDim.x + threadIdx.x;
    if (idx >= CIN * CIN * 9) return;
    int kk = idx % 9;
    int ic = (idx / 9) % CIN;
    int oc = idx / (9 * CIN);
    g_wt[((size_t)ic * 9 + kk) * CIN + oc] = w[idx];
}

// ---------------- 1: 3x3 conv + bias + relu, fp32 FFMA2, cp.async pipeline ---
// Identical compute & accumulation order to the proven R3 kernel (bitwise-
// identical output); staging converted to double-buffered cp.async so the
// global-load latency is hidden behind the FFMA2 stream.
// Block: 64 oc (blockIdx.x) x 4 rows (blockIdx.y) x batch (blockIdx.z), 256 thr.
// Thread tile: 8 oc x 8 px; warp-uniform weight broadcasts.
#define IN_WORDS (8 * 6 * 68)          // 3264 (66 used cols, stride 68 for 16B)
#define W_WORDS (8 * 9 * 64)           // 4608
#define BUF_WORDS (IN_WORDS + W_WORDS) // 7872
#define CONV_SMEM (2 * BUF_WORDS * 4)  // 62976 bytes

__global__ __launch_bounds__(256, 2) void conv3x3_kernel(
    const float* __restrict__ x, const float* __restrict__ bias) {
    extern __shared__ float sm[];
    const int octile = blockIdx.x;   // 0..7   (oc base = octile*64)
    const int y0 = blockIdx.y * 4;   // rows y0..y0+3
    const int b = blockIdx.z;        // 0..7
    const int tid = threadIdx.x;
    const int tx = tid & 31;
    const int ty = tid >> 5;         // warp id = oc subgroup 0..7
    const int r_out = tx >> 3;       // 0..3 row within block
    const int X0 = (tx & 7) * 8;     // x base, 8 px per thread

    const float* xb = x + (size_t)b * CIN * HWP;

    // stage chunk (8 input channels starting at icg) into buffer buf
    auto stage = [&](int buf, int icg) {
        float* s_in = sm + buf * BUF_WORDS;
        float* s_wt = s_in + IN_WORDS;
        // inputs: 8 ic x 6 rows x 66 cols (halo'd) via 4B cp.async (zero-fill OOB)
        for (int t = tid; t < 8 * 6 * 66; t += 256) {
            int xx = t % 66;
            int r = (t / 66) % 6;
            int ic = t / 396;
            int gy = y0 + r - 1;
            int gx = xx - 1;
            bool ok = ((unsigned)gy < 64u) && ((unsigned)gx < 64u);
            const float* src = ok ? &xb[(size_t)(icg + ic) * HWP + gy * 64 + gx] : xb;
            uint32_t dst = smem_u32(&s_in[(ic * 6 + r) * 68 + xx]);
            asm volatile("cp.async.ca.shared.global [%0], [%1], 4, %2;"
                         :: "r"(dst), "l"(src), "r"(ok ? 4u : 0u) : "memory");
        }
        // weights: 8 ic x 9 taps x 64 oc via 16B cp.async (1152 chunks)
        const float* wsrc = g_wt + (size_t)icg * 9 * CIN + octile * 64;
        for (int t = tid; t < 1152; t += 256) {
            int c4 = t & 15;
            int kk = (t >> 4) % 9;
            int ic = t / 144;
            const float* src = wsrc + (size_t)(ic * 9 + kk) * CIN + c4 * 4;
            uint32_t dst = smem_u32(&s_wt[(ic * 9 + kk) * 64 + c4 * 4]);
            asm volatile("cp.async.cg.shared.global [%0], [%1], 16;"
                         :: "r"(dst), "l"(src) : "memory");
        }
    };

    // acc2[g][i]: packed (acc[oc=2g], acc[oc=2g+1]) for px i
    ull acc2[4][8];
#pragma unroll
    for (int g = 0; g < 4; g++)
#pragma unroll
        for (int i = 0; i < 8; i++) acc2[g][i] = pack2(0.f, 0.f);

    stage(0, 0);
    CP_COMMIT();

    for (int s = 0; s < 64; s++) {
        if (s + 1 < 64) {
            stage((s + 1) & 1, (s + 1) * 8);
            CP_COMMIT();
            CP_WAIT1();
        } else {
            CP_WAIT0();
        }
        __syncthreads();

        const float* s_in = sm + (s & 1) * BUF_WORDS;
        const float* s_wt = s_in + IN_WORDS;

#pragma unroll
        for (int ic = 0; ic < 8; ic++) {
#pragma unroll
            for (int ky = 0; ky < 3; ky++) {
                // 10 input cols X0..X0+9 (row stride 68 words = 16B aligned)
                const float* irow = &s_in[(ic * 6 + r_out + ky) * 68 + X0];
                float4 f0 = *(const float4*)(irow);
                float4 f1 = *(const float4*)(irow + 4);
                float2 f2 = *(const float2*)(irow + 8);
                ull xp[10];
                xp[0] = pack2(f0.x, f0.x); xp[1] = pack2(f0.y, f0.y);
                xp[2] = pack2(f0.z, f0.z); xp[3] = pack2(f0.w, f0.w);
                xp[4] = pack2(f1.x, f1.x); xp[5] = pack2(f1.y, f1.y);
                xp[6] = pack2(f1.z, f1.z); xp[7] = pack2(f1.w, f1.w);
                xp[8] = pack2(f2.x, f2.x); xp[9] = pack2(f2.y, f2.y);
#pragma unroll
                for (int kx = 0; kx < 3; kx++) {
                    // 8 oc weights, warp-uniform address (ty const per warp)
                    const ull* wp = (const ull*)&s_wt[(ic * 9 + ky * 3 + kx) * 64 + ty * 8];
                    ull w01 = wp[0];
                    ull w23 = wp[1];
                    ull w45 = wp[2];
                    ull w67 = wp[3];
#pragma unroll
                    for (int i = 0; i < 8; i++) {
                        ffma2(acc2[0][i], xp[i + kx], w01);
                        ffma2(acc2[1][i], xp[i + kx], w23);
                        ffma2(acc2[2][i], xp[i + kx], w45);
                        ffma2(acc2[3][i], xp[i + kx], w67);
                    }
                }
            }
        }
        __syncthreads();
    }

    const int ocbase = octile * 64 + ty * 8;
    const int yrow = y0 + r_out;
#pragma unroll
    for (int g = 0; g < 4; g++) {
        float bv0 = bias[ocbase + 2 * g];
        float bv1 = bias[ocbase + 2 * g + 1];
        float r0[8], r1[8];
#pragma unroll
        for (int i = 0; i < 8; i++) {
            float2 u = unpack2(acc2[g][i]);
            r0[i] = fmaxf(u.x + bv0, 0.f);
            r1[i] = fmaxf(u.y + bv1, 0.f);
        }
        float* d0 = &g_h[((size_t)(b * CIN + ocbase + 2 * g)) * HWP + yrow * WW + X0];
        float* d1 = &g_h[((size_t)(b * CIN + ocbase + 2 * g + 1)) * HWP + yrow * WW + X0];
        *(float4*)(d0)     = make_float4(r0[0], r0[1], r0[2], r0[3]);
        *(float4*)(d0 + 4) = make_float4(r0[4], r0[5], r0[6], r0[7]);
        *(float4*)(d1)     = make_float4(r1[0], r1[1], r1[2], r1[3]);
        *(float4*)(d1 + 4) = make_float4(r1[4], r1[5], r1[6], r1[7]);
    }
}

// ---------------- 2: heads (1x1 convs) + proposal prep -----------------------
__global__ __launch_bounds__(128) void heads_kernel(
    const float* __restrict__ loc_w, const float* __restrict__ loc_b,
    const float* __restrict__ cls_w, const float* __restrict__ cls_b,
    const int* __restrict__ imh, const int* __restrict__ imw,
    float* __restrict__ out) {
    const int b = blockIdx.x >> 5;
    const int p = ((blockIdx.x & 31) << 7) + threadIdx.x;  // 0..4095

    __shared__ float s_w[64][56];  // padded to 56 for 8B alignment of pairs

    ull acc2[27];
#pragma unroll
    for (int m = 0; m < 27; m++) acc2[m] = pack2(0.f, 0.f);

    const float* hb = g_h + (size_t)b * CIN * HWP + p;

    for (int icg = 0; icg < CIN; icg += 64) {
        __syncthreads();
        for (int t = threadIdx.x; t < 64 * 54; t += 128) {
            int m = t % 54;
            int ic = t / 54;
            float wv = (m < 36) ? loc_w[m * CIN + icg + ic]
                                : cls_w[(m - 36) * CIN + icg + ic];
            s_w[ic][m] = wv;
        }
        __syncthreads();
        for (int ic = 0; ic < 64; ic++) {
            float hv = hb[(size_t)(icg + ic) * HWP];
            ull hp = pack2(hv, hv);
            const ull* wrow = (const ull*)&s_w[ic][0];
#pragma unroll
            for (int m = 0; m < 27; m++) ffma2(acc2[m], hp, wrow[m]);
        }
    }

    float acc[54];
#pragma unroll
    for (int m = 0; m < 27; m++) {
        float2 u = unpack2(acc2[m]);
        acc[2 * m] = u.x;
        acc[2 * m + 1] = u.y;
    }

    const float fh = (float)(*imh);
    const float fw = (float)(*imw);
    const int py = p >> 6, px = p & 63;
    const float sy = (float)py * 16.0f;
    const float sx = (float)px * 16.0f;

    const size_t cls_base = OFF_CLS + ((size_t)b * NA + (size_t)p * 9) * 2;
    const size_t loc_base = OFF_LOC + ((size_t)b * NA + (size_t)p * 9) * 4;

#pragma unroll
    for (int a = 0; a < 9; a++) {
        float dy = acc[4 * a + 0] + loc_b[4 * a + 0];
        float dx = acc[4 * a + 1] + loc_b[4 * a + 1];
        float dh = acc[4 * a + 2] + loc_b[4 * a + 2];
        float dw = acc[4 * a + 3] + loc_b[4 * a + 3];
        out[loc_base + a * 4 + 0] = dy;
        out[loc_base + a * 4 + 1] = dx;
        out[loc_base + a * 4 + 2] = dh;
        out[loc_base + a * 4 + 3] = dw;

        float v0 = acc[36 + 2 * a + 0] + cls_b[2 * a + 0];
        float v1 = acc[36 + 2 * a + 1] + cls_b[2 * a + 1];
        float c0 = 1.f / (1.f + expf(-v0));
        float c1 = 1.f / (1.f + expf(-v1));
        out[cls_base + a * 2 + 0] = c0;
        out[cls_base + a * 2 + 1] = c1;

        // anchor decode + clip + min-size filter
        float a0 = -c_h2[a] + sy;
        float a1 = -c_w2[a] + sx;
        float a2 = c_h2[a] + sy;
        float a3 = c_w2[a] + sx;
        float hh = a2 - a0;
        float ww = a3 - a1;
        float cy = a0 + 0.5f * hh;
        float cx = a1 + 0.5f * ww;
        cy = cy + dy * hh;
        cx = cx + dx * ww;
        hh = hh * expf(dh);
        ww = ww * expf(dw);
        float r0 = cy - 0.5f * hh;
        float r1 = cx - 0.5f * ww;
        float r2 = cy + 0.5f * hh;
        float r3 = cx + 0.5f * ww;
        r0 = fminf(fmaxf(r0, 0.f), fh);
        r1 = fminf(fmaxf(r1, 0.f), fw);
        r2 = fminf(fmaxf(r2, 0.f), fh);
        r3 = fminf(fmaxf(r3, 0.f), fw);
        float hs = r2 - r0;
        float ws = r3 - r1;
        bool valid = (hs >= 16.0f) && (ws >= 16.0f);
        float sc = valid ? c1 : NEGINF;

        int i = p * 9 + a;
        float4 rb;
        rb.x = r0; rb.y = r1; rb.z = r2; rb.w = r3;
        *(float4*)&g_roi[((size_t)b * NA + i) * 4] = rb;
        g_score[(size_t)b * NA + i] = sc;
        unsigned uu = __float_as_uint(sc);
        uu = (uu & 0x80000000u) ? ~uu : (uu | 0x80000000u);
        g_keys[(size_t)b * NSORT + i] =
            ((ull)uu << 32) | (unsigned)(0xFFFFFFFFu - (unsigned)i);
    }
    // padding keys (7 per thread: 4096*7 = 28672 = 65536-36864)
#pragma unroll
    for (int k2 = 0; k2 < 7; k2++)
        g_keys[(size_t)b * NSORT + NA + p * 7 + k2] = 0ull;
}

// ---------------- 3: bitonic sort, smem-tiled --------------------------------
#define TILE 4096

__global__ __launch_bounds__(1024) void sort_phase1_kernel() {
    __shared__ ull s[TILE];
    const int batch = blockIdx.x >> 4;
    const int tile = blockIdx.x & 15;
    ull* d = g_keys + (size_t)batch * NSORT + (size_t)tile * TILE;
    const int gbase = tile * TILE;

    for (int t = threadIdx.x; t < TILE; t += 1024) s[t] = d[t];
    __syncthreads();

    for (int k = 2; k <= TILE; k <<= 1) {
        for (int j = k >> 1; j > 0; j >>= 1) {
            for (int t = threadIdx.x; t < TILE; t += 1024) {
                int ixj = t ^ j;
                if (ixj > t) {
                    ull A = s[t];
                    ull Bv = s[ixj];
                    bool up = (((gbase + t) & k) == 0);
                    if (up ? (A > Bv) : (A < Bv)) {
                        s[t] = Bv;
                        s[ixj] = A;
                    }
                }
            }
            __syncthreads();
        }
    }
    for (int t = threadIdx.x; t < TILE; t += 1024) d[t] = s[t];
}

__global__ __launch_bounds__(256) void sort_gstep_kernel(int k, int j) {
    int idx = blockIdx.x * blockDim.x + threadIdx.x;
    int b = idx >> 16;
    int t = idx & (NSORT - 1);
    ull* d = g_keys + (size_t)b * NSORT;
    int ixj = t ^ j;
    if (ixj > t) {
        ull A = d[t];
        ull Bv = d[ixj];
        bool up = ((t & k) == 0);
        if (up ? (A > Bv) : (A < Bv)) {
            d[t] = Bv;
            d[ixj] = A;
        }
    }
}

__global__ __launch_bounds__(1024) void sort_sphase_kernel(int k) {
    __shared__ ull s[TILE];
    const int batch = blockIdx.x >> 4;
    const int tile = blockIdx.x & 15;
    ull* d = g_keys + (size_t)batch * NSORT + (size_t)tile * TILE;
    const int gbase = tile * TILE;

    for (int t = threadIdx.x; t < TILE; t += 1024) s[t] = d[t];
    __syncthreads();

    for (int j = TILE / 2; j > 0; j >>= 1) {
        for (int t = threadIdx.x; t < TILE; t += 1024) {
            int ixj = t ^ j;
            if (ixj > t) {
                ull A = s[t];
                ull Bv = s[ixj];
                bool up = (((gbase + t) & k) == 0);
                if (up ? (A > Bv) : (A < Bv)) {
                    s[t] = Bv;
                    s[ixj] = A;
                }
            }
        }
        __syncthreads();
    }
    for (int t = threadIdx.x; t < TILE; t += 1024) d[t] = s[t];
}

// ---------------- 4: per-batch NMS -------------------------------------------
__global__ __launch_bounds__(256) void nms_kernel(float* __restrict__ out) {
    __shared__ float ss[NPRE];
    __shared__ unsigned char smask[NPRE];
    __shared__ int s_pick;

    const int b = blockIdx.x;
    const ull* kb = g_keys + (size_t)b * NSORT;
    float* nb = g_nbox + (size_t)b * NPRE * 4;

    for (int t = threadIdx.x; t < NPRE; t += blockDim.x) {
        ull key = kb[NSORT - 1 - t];
        unsigned ai = 0xFFFFFFFFu - (unsigned)(key & 0xFFFFFFFFull);
        *(float4*)&nb[(size_t)t * 4] =
            *(const float4*)&g_roi[((size_t)b * NA + ai) * 4];
        ss[t] = g_score[(size_t)b * NA + ai];
        smask[t] = 0;
    }
    for (int t = threadIdx.x; t < NPOST; t += blockDim.x)
        out[OFF_IDX + (size_t)b * NPOST + t] = (float)b;
    __syncthreads();

    int ptr = 0;
    for (int pick = 0; pick < NPOST; pick++) {
        if (threadIdx.x == 0) {
            while (ptr < NPRE && smask[ptr]) ptr++;
            if (ptr < NPRE && ss[ptr] != NEGINF) {
                s_pick = ptr;
                smask[ptr] = 1;
            } else {
                s_pick = -1;
            }
        }
        __syncthreads();
        int p = s_pick;
        if (p < 0) {
            int rem = (NPOST - pick) * 4;
            for (int t = threadIdx.x; t < rem; t += blockDim.x)
                out[OFF_ROI + ((size_t)b * NPOST + pick) * 4 + t] = 0.f;
            break;
        }
        float4 pb = *(const float4*)&nb[(size_t)p * 4];
        if (threadIdx.x == 0) {
            out[OFF_ROI + ((size_t)b * NPOST + pick) * 4 + 0] = pb.x;
            out[OFF_ROI + ((size_t)b * NPOST + pick) * 4 + 1] = pb.y;
            out[OFF_ROI + ((size_t)b * NPOST + pick) * 4 + 2] = pb.z;
            out[OFF_ROI + ((size_t)b * NPOST + pick) * 4 + 3] = pb.w;
        }
        float parea = (pb.z - pb.x) * (pb.w - pb.y);
        for (int j = p + 1 + threadIdx.x; j < NPRE; j += blockDim.x) {
            if (!smask[j]) {
                float4 q = *(const float4*)&nb[(size_t)j * 4];
                float yy1 = fmaxf(q.x, pb.x);
                float xx1 = fmaxf(q.y, pb.y);
                float yy2 = fminf(q.z, pb.z);
                float xx2 = fminf(q.w, pb.w);
                float inter = fmaxf(yy2 - yy1, 0.f) * fmaxf(xx2 - xx1, 0.f);
                float qarea = (q.z - q.x) * (q.w - q.y);
                float iou = inter / (qarea + parea - inter + 1e-9f);
                if (iou > 0.7f) smask[j] = 1;
            }
        }
        __syncthreads();
    }
}

// ---------------- launcher ---------------------------------------------------
extern "C" void kernel_launch(void* const* d_in, const int* in_sizes, int n_in,
                              void* d_out, int out_size) {
    const float* x = (const float*)d_in[0];
    const float* conv_w = (const float*)d_in[1];
    const float* conv_b = (const float*)d_in[2];
    const float* loc_w = (const float*)d_in[3];
    const float* loc_b = (const float*)d_in[4];
    const float* cls_w = (const float*)d_in[5];
    const float* cls_b = (const float*)d_in[6];
    const int* imh = (const int*)d_in[7];
    const int* imw = (const int*)d_in[8];
    float* out = (float*)d_out;

    cudaFuncSetAttribute(conv3x3_kernel,
                         cudaFuncAttributeMaxDynamicSharedMemorySize, CONV_SMEM);

    wtrans_kernel<<<(CIN * CIN * 9 + 255) / 256, 256>>>(conv_w);
    conv3x3_kernel<<<dim3(8, 16, 8), 256, CONV_SMEM>>>(x, conv_b);
    heads_kernel<<<256, 128>>>(loc_w, loc_b, cls_w, cls_b, imh, imw, out);

    sort_phase1_kernel<<<128, 1024>>>();
    for (int k = 8192; k <= NSORT; k <<= 1) {
        for (int j = k >> 1; j >= TILE; j >>= 1)
            sort_gstep_kernel<<<(BB * NSORT) / 256, 256>>>(k, j);
        sort_sphase_kernel<<<128, 1024>>>(k);
    }

    nms_kernel<<<8, 256>>>(out);
}